// round 8
// baseline (speedup 1.0000x reference)
#include <cuda_runtime.h>
#include <cuda_bf16.h>
#include <cstdint>
#include <cstddef>

// Problem constants
#define BB    32
#define DD    512
#define NN    4096
#define KK    64
#define DTILE 64           // d rows per CTA
#define NC    64           // n elements per stage
#define NITER (NN / NC)    // 64

// Static smem layout: a-tile stages (bf16, 64 x 128B = 8KB each) @0/@8192,
// nsplit reduction buffer 16KB @16384, asum 256B @32768.
#define OFF_RED   16384
#define OFF_ASUM  32768
#define SMEM_SIZE 33280

__device__ __forceinline__ uint32_t smem_u32(const void* p) {
    uint32_t a;
    asm("{ .reg .u64 t; cvta.to.shared.u64 t, %1; cvt.u32.u64 %0, t; }" : "=r"(a) : "l"(p));
    return a;
}

__device__ __forceinline__ void sts16u(uint32_t addr, uint32_t a, uint32_t b,
                                       uint32_t c, uint32_t d) {
    asm volatile("st.shared.v4.b32 [%0], {%1, %2, %3, %4};"
                 :: "r"(addr), "r"(a), "r"(b), "r"(c), "r"(d) : "memory");
}

__device__ __forceinline__ void sts16(uint32_t addr, float4 v) {
    asm volatile("st.shared.v4.b32 [%0], {%1, %2, %3, %4};"
                 :: "r"(addr), "f"(v.x), "f"(v.y), "f"(v.z), "f"(v.w) : "memory");
}

__device__ __forceinline__ float4 lds16(uint32_t addr) {
    float4 v;
    asm volatile("ld.shared.v4.b32 {%0, %1, %2, %3}, [%4];"
                 : "=f"(v.x), "=f"(v.y), "=f"(v.z), "=f"(v.w) : "r"(addr));
    return v;
}

__device__ __forceinline__ void ldsm4(uint32_t* r, uint32_t addr) {
    asm volatile("ldmatrix.sync.aligned.m8n8.x4.shared.b16 {%0,%1,%2,%3}, [%4];"
                 : "=r"(r[0]), "=r"(r[1]), "=r"(r[2]), "=r"(r[3]) : "r"(addr));
}

__device__ __forceinline__ void mma16816(float* d, const uint32_t* a, uint32_t b0, uint32_t b1) {
    asm volatile(
        "mma.sync.aligned.m16n8k16.row.col.f32.bf16.bf16.f32 "
        "{%0,%1,%2,%3}, {%4,%5,%6,%7}, {%8,%9}, {%0,%1,%2,%3};"
        : "+f"(d[0]), "+f"(d[1]), "+f"(d[2]), "+f"(d[3])
        : "r"(a[0]), "r"(a[1]), "r"(a[2]), "r"(a[3]), "r"(b0), "r"(b1));
}

__device__ __forceinline__ uint32_t cvt2(float a, float b) {
    __nv_bfloat162 p = __floats2bfloat162_rn(a, b);
    return *reinterpret_cast<uint32_t*>(&p);
}

// Load this thread's x A-fragment fp32 pairs for one stage.
// f[i*4+q]: m-frag i (rows +16i), q = (row+8?)<<0 | (k+8?)<<1.
__device__ __forceinline__ void ldx(float2* f, const float* p) {
#pragma unroll
    for (int i = 0; i < 2; i++)
#pragma unroll
        for (int q = 0; q < 4; q++)
            f[i * 4 + q] = *reinterpret_cast<const float2*>(
                p + (size_t)i * 16 * NN + (size_t)(q & 1) * 8 * NN + (q >> 1) * 8);
}

__device__ __forceinline__ float sum8(const float4& a, const float4& b) {
    return ((a.x + a.y) + (a.z + a.w)) + ((b.x + b.y) + (b.z + b.w));
}

// ---------------------------------------------------------------------------
// One 512-thread CTA per (b, dt): D[64 d, 64 k] = X @ Abar^T via mma.sync
// bf16. x NEVER goes through smem: each thread LDGs exactly its own
// A-fragment fp32 pairs (layout derived from the proven ldsm quadrant map)
// and converts in-register. Only the a_bar tile is staged (bf16, swizzled)
// for B-side ldmatrix. Warp grid 2(m) x 2(n) x 4(ksplit). Scheduling: no op
// in iteration `it` consumes an iteration-`it` load.
// ---------------------------------------------------------------------------
__global__ void __launch_bounds__(512, 1)
vlad_main(const float* __restrict__ x, const float* __restrict__ ab,
          const float* __restrict__ cmat, float* __restrict__ out) {
    __shared__ __align__(1024) char smem[SMEM_SIZE];
    const uint32_t sb = smem_u32(smem);
    float* asum_s = reinterpret_cast<float*>(smem + OFF_ASUM);

    const int tid = threadIdx.x;
    const int warp = tid >> 5, lane = tid & 31;
    const int b  = blockIdx.x >> 3;
    const int dt = blockIdx.x & 7;

    const int wm = (warp & 1) * 32;
    const int wn = ((warp >> 1) & 1) * 32;
    const int nh = warp >> 2;                 // k-step (of 4) this warp owns

    // a-tile staging: one 32B chunk per thread (row = tid>>3, 8 fp32)
    const int arow = tid >> 3, c8 = tid & 7;
    const float* ap = ab + ((size_t)b * KK + arow) * NN + c8 * 8;
    const uint32_t sw = (uint32_t)((arow << 7) + (c8 << 4)) ^ ((uint32_t)(arow & 7) << 4);

    // x fragment base: rows dt*64 + wm + (lane>>2), cols nh*16 + 2*(lane&3)
    const float* xq = x + ((size_t)b * DD + dt * DTILE + wm + (lane >> 2)) * NN
                        + nh * 16 + 2 * (lane & 3);

    // B ldsm offsets (within an 8KB stage buffer), k-column folded in
    const int g = lane >> 3, rr = lane & 7;
    uint32_t offB[2];
#pragma unroll
    for (int nb = 0; nb < 2; nb++) {
        int rowp = wn + nb * 16 + (g >> 1) * 8 + rr;
        uint32_t col = ((uint32_t)((g & 1) * 16) ^ ((uint32_t)nh << 5))
                       ^ ((uint32_t)(rowp & 7) << 4);
        offB[nb] = (uint32_t)(rowp << 7) + col;
    }

    float4 accv[8];
#pragma unroll
    for (int i = 0; i < 8; i++) accv[i] = make_float4(0.f, 0.f, 0.f, 0.f);
    float asum_p = 0.f;

    float4 a0, a1;           // a-tile staging regs (distance 2)
    float2 xf0[8], xf1[8];   // x-fragment double buffer (distance 1)

    // ---- prologue ----
    a0 = *reinterpret_cast<const float4*>(ap);
    a1 = *reinterpret_cast<const float4*>(ap + 4);
    asum_p += sum8(a0, a1);
    sts16u(sb + sw, cvt2(a0.x, a0.y), cvt2(a0.z, a0.w), cvt2(a1.x, a1.y), cvt2(a1.z, a1.w));
    a0 = *reinterpret_cast<const float4*>(ap + NC);
    a1 = *reinterpret_cast<const float4*>(ap + NC + 4);
    ldx(xf0, xq);            // x frags, stage 0

#define BODY(IT, XFC, XFN)                                                          \
    {                                                                               \
        const int it_ = (IT);                                                       \
        __syncthreads();                                                            \
        if (it_ + 1 < NITER) {                                                      \
            asum_p += sum8(a0, a1);                                                 \
            const uint32_t ns = sb + (uint32_t)(((it_ + 1) & 1) << 13);             \
            sts16u(ns + sw, cvt2(a0.x, a0.y), cvt2(a0.z, a0.w),                     \
                   cvt2(a1.x, a1.y), cvt2(a1.z, a1.w));                             \
        }                                                                           \
        if (it_ + 2 < NITER) {                                                      \
            const float* p_ = ap + (it_ + 2) * NC;                                  \
            a0 = *reinterpret_cast<const float4*>(p_);                              \
            a1 = *reinterpret_cast<const float4*>(p_ + 4);                          \
        }                                                                           \
        if (it_ + 1 < NITER) ldx(XFN, xq + (it_ + 1) * NC);                         \
        const uint32_t bs = sb + (uint32_t)((it_ & 1) << 13);                       \
        uint32_t bF0[4], bF1[4];                                                    \
        ldsm4(bF0, bs + offB[0]);                                                   \
        ldsm4(bF1, bs + offB[1]);                                                   \
        _Pragma("unroll")                                                           \
        for (int i_ = 0; i_ < 2; i_++) {                                            \
            uint32_t aF[4];                                                         \
            aF[0] = cvt2((XFC)[i_ * 4 + 0].x, (XFC)[i_ * 4 + 0].y);                 \
            aF[1] = cvt2((XFC)[i_ * 4 + 1].x, (XFC)[i_ * 4 + 1].y);                 \
            aF[2] = cvt2((XFC)[i_ * 4 + 2].x, (XFC)[i_ * 4 + 2].y);                 \
            aF[3] = cvt2((XFC)[i_ * 4 + 3].x, (XFC)[i_ * 4 + 3].y);                 \
            mma16816(reinterpret_cast<float*>(&accv[i_ * 4 + 0]), aF, bF0[0], bF0[1]); \
            mma16816(reinterpret_cast<float*>(&accv[i_ * 4 + 1]), aF, bF0[2], bF0[3]); \
            mma16816(reinterpret_cast<float*>(&accv[i_ * 4 + 2]), aF, bF1[0], bF1[1]); \
            mma16816(reinterpret_cast<float*>(&accv[i_ * 4 + 3]), aF, bF1[2], bF1[3]); \
        }                                                                           \
    }

    for (int it = 0; it < NITER; it += 2) {
        BODY(it, xf0, xf1)
        BODY(it + 1, xf1, xf0)
    }
#undef BODY

    // ---- a_sum: 8 lanes (same arow) share a k-row ----
#pragma unroll
    for (int o = 1; o < 8; o <<= 1)
        asum_p += __shfl_xor_sync(0xFFFFFFFFu, asum_p, o);
    if ((lane & 7) == 0) asum_s[arow] = asum_p;

    // ---- ksplit reduction chain: nh 3 -> 2 -> 1 -> 0 ----
    const uint32_t gaddr = sb + OFF_RED + (uint32_t)(((warp & 3) * 32 + lane) * 128);
#pragma unroll
    for (int rch = 3; rch >= 1; --rch) {
        if (nh == rch) {
#pragma unroll
            for (int f = 0; f < 8; f++)
                sts16(gaddr + (uint32_t)((f ^ (lane & 7)) << 4), accv[f]);
        }
        __syncthreads();
        if (nh == rch - 1) {
#pragma unroll
            for (int f = 0; f < 8; f++) {
                float4 p = lds16(gaddr + (uint32_t)((f ^ (lane & 7)) << 4));
                accv[f].x += p.x; accv[f].y += p.y; accv[f].z += p.z; accv[f].w += p.w;
            }
        }
        __syncthreads();
    }

    // ---- epilogue (nh==0 warps cover all (wm, wn)) ----
    if (nh == 0) {
        const int mrow = lane >> 2, ncol = (lane & 3) * 2;
#pragma unroll
        for (int i = 0; i < 2; i++) {
#pragma unroll
            for (int j = 0; j < 4; j++) {
                const float* apv = reinterpret_cast<const float*>(&accv[i * 4 + j]);
                const int k0 = wn + j * 8 + ncol;
                const int d0 = dt * DTILE + wm + i * 16 + mrow;
                const float as0 = asum_s[k0], as1 = asum_s[k0 + 1];
#pragma unroll
                for (int rrr = 0; rrr < 2; rrr++) {
                    const int d = d0 + rrr * 8;
                    float v0 = apv[rrr * 2 + 0] - as0 * __ldg(cmat + (size_t)k0 * DD + d);
                    float v1 = apv[rrr * 2 + 1] - as1 * __ldg(cmat + (size_t)(k0 + 1) * DD + d);
                    out[(size_t)d * KK * BB + (size_t)k0 * BB + b] = v0;
                    out[(size_t)d * KK * BB + (size_t)(k0 + 1) * BB + b] = v1;
                }
            }
        }
    }
}

extern "C" void kernel_launch(void* const* d_in, const int* in_sizes, int n_in,
                              void* d_out, int out_size) {
    (void)in_sizes; (void)n_in; (void)out_size;
    const float* x  = (const float*)d_in[0];
    const float* ab = (const float*)d_in[1];
    const float* c  = (const float*)d_in[2];
    float* out = (float*)d_out;

    vlad_main<<<BB * 8, 512>>>(x, ab, c, out);
}

// round 9
// speedup vs baseline: 2.3791x; 2.3791x over previous
#include <cuda_runtime.h>
#include <cuda_bf16.h>
#include <cstdint>
#include <cstddef>

// Problem constants
#define BB    32
#define DD    512
#define NN    4096
#define KK    64
#define DTILE 64           // d rows per CTA
#define NC    64           // n elements per stage (64 fp32 -> 64 bf16 = 128B row)
#define NITER (NN / NC)    // 64

// SMEM stage layout: x tile 64 rows x 128B = 8KB, a tile 64 x 128B = 8KB
#define STG_BYTES  16384
#define STG_AOFF   8192
#define OFF_ASUM   (2 * STG_BYTES)          // 64 floats
#define SMEM_TOTAL (OFF_ASUM + 256 + 1024)  // + alignment slack

__device__ __forceinline__ uint32_t smem_u32(const void* p) {
    uint32_t a;
    asm("{ .reg .u64 t; cvta.to.shared.u64 t, %1; cvt.u32.u64 %0, t; }" : "=r"(a) : "l"(p));
    return a;
}

__device__ __forceinline__ void sts8(uint32_t addr, uint32_t a, uint32_t b) {
    asm volatile("st.shared.v2.b32 [%0], {%1, %2};" :: "r"(addr), "r"(a), "r"(b) : "memory");
}

__device__ __forceinline__ void sts16(uint32_t addr, float4 v) {
    asm volatile("st.shared.v4.b32 [%0], {%1, %2, %3, %4};"
                 :: "r"(addr), "f"(v.x), "f"(v.y), "f"(v.z), "f"(v.w) : "memory");
}

__device__ __forceinline__ float4 lds16(uint32_t addr) {
    float4 v;
    asm volatile("ld.shared.v4.b32 {%0, %1, %2, %3}, [%4];"
                 : "=f"(v.x), "=f"(v.y), "=f"(v.z), "=f"(v.w) : "r"(addr));
    return v;
}

__device__ __forceinline__ void ldsm4(uint32_t* r, uint32_t addr) {
    asm volatile("ldmatrix.sync.aligned.m8n8.x4.shared.b16 {%0,%1,%2,%3}, [%4];"
                 : "=r"(r[0]), "=r"(r[1]), "=r"(r[2]), "=r"(r[3]) : "r"(addr));
}

__device__ __forceinline__ void mma16816(float* d, const uint32_t* a, uint32_t b0, uint32_t b1) {
    asm volatile(
        "mma.sync.aligned.m16n8k16.row.col.f32.bf16.bf16.f32 "
        "{%0,%1,%2,%3}, {%4,%5,%6,%7}, {%8,%9}, {%0,%1,%2,%3};"
        : "+f"(d[0]), "+f"(d[1]), "+f"(d[2]), "+f"(d[3])
        : "r"(a[0]), "r"(a[1]), "r"(a[2]), "r"(a[3]), "r"(b0), "r"(b1));
}

__device__ __forceinline__ void cvt4(const float4& v, uint32_t& lo, uint32_t& hi) {
    __nv_bfloat162 l = __floats2bfloat162_rn(v.x, v.y);
    __nv_bfloat162 h = __floats2bfloat162_rn(v.z, v.w);
    lo = *reinterpret_cast<uint32_t*>(&l);
    hi = *reinterpret_cast<uint32_t*>(&h);
}

// ---------------------------------------------------------------------------
// Merge of the two best kernels:
//  - R6's fully line-coalesced loader (16 threads x 16B cover whole 128B
//    lines; 4 wavefronts per LDG.128 instr), STS swizzle, 2m x 2n x 2ksplit
//    warp tiling, nsplit reduction, epilogue.
//  - R7's schedule: at the top of each iteration, the registers loaded one
//    iteration ago are folded into a_sum and STS'd (WAR pins the fold before
//    the LDG refill), so NOTHING in iteration `it` consumes iteration-`it`
//    loads. LDG prefetch distance = 2 stages.
// Per CTA (b, dt): D[64 d, 64 k] = X(64 x 4096) @ Abar^T, bf16 mma.sync,
// fp32 epilogue V = wx - a_sum[k]*c[k,d] -> out[d,k,b].
// ---------------------------------------------------------------------------
__global__ void __launch_bounds__(256, 2)
vlad_main(const float* __restrict__ x, const float* __restrict__ ab,
          const float* __restrict__ cmat, float* __restrict__ out) {
    extern __shared__ __align__(16) char smem_raw[];
    const uint32_t sbr = smem_u32(smem_raw);
    const uint32_t sb0 = (sbr + 1023) & ~1023u;
    float* asum_s = reinterpret_cast<float*>(smem_raw + (sb0 - sbr) + OFF_ASUM);

    const int tid  = threadIdx.x;
    const int warp = tid >> 5, lane = tid & 31;
    const int b  = blockIdx.x >> 3;
    const int dt = blockIdx.x & 7;

    const float* xbase = x  + ((size_t)b * DD + (size_t)dt * DTILE) * NN;
    const float* abase = ab + (size_t)b * KK * NN;

    // STS swizzled offsets: 1024 float4 per tile, 4/thread; ci = tid + 256j
    // -> row = ci>>4 (16 threads per 64-float row), c4 = ci&15 (16B each).
    uint32_t sts_off[4];
#pragma unroll
    for (int j = 0; j < 4; j++) {
        int ci = tid + 256 * j, row = ci >> 4, c4 = ci & 15;
        uint32_t off = (uint32_t)((row << 7) + (c4 << 3));
        sts_off[j] = off ^ ((off >> 3) & 0x70);
    }

    // Warp decomposition: 2(m) x 2(n) x 2(nsplit)
    const int wm = (warp & 1) * 32;
    const int wn = ((warp >> 1) & 1) * 32;
    const int nh = warp >> 2;                 // contraction half: k-steps 2nh, 2nh+1

    // ldmatrix source offsets
    const int g = lane >> 3, r = lane & 7;
    uint32_t offA[2], offB[2];
#pragma unroll
    for (int i = 0; i < 2; i++) {
        int row = wm + i * 16 + (g & 1) * 8 + r;
        uint32_t gk = (uint32_t)((g >> 1) * 16);
        offA[i] = (uint32_t)(row << 7) + (gk ^ (uint32_t)((row & 7) << 4));
    }
#pragma unroll
    for (int nb = 0; nb < 2; nb++) {
        int row = wn + nb * 16 + (g >> 1) * 8 + r;
        uint32_t gk = (uint32_t)((g & 1) * 16);
        offB[nb] = (uint32_t)(row << 7) + (gk ^ (uint32_t)((row & 7) << 4)) + STG_AOFF;
    }

    // Accumulators: 2 m-frags x 4 n-frags, one float4 each = 32 regs
    float4 accv[8];
#pragma unroll
    for (int i = 0; i < 8; i++) accv[i] = make_float4(0.f, 0.f, 0.f, 0.f);
    float asum_p[4] = {0.f, 0.f, 0.f, 0.f};

    float4 xr[4], ar[4];

    // ---- prologue ----
    // stage 0: load, fold, STS into buf0
#pragma unroll
    for (int j = 0; j < 4; j++) {
        int ci = tid + 256 * j, row = ci >> 4, c4 = ci & 15;
        xr[j] = *reinterpret_cast<const float4*>(xbase + (size_t)row * NN + (c4 << 2));
        ar[j] = *reinterpret_cast<const float4*>(abase + (size_t)row * NN + (c4 << 2));
    }
#pragma unroll
    for (int j = 0; j < 4; j++) {
        uint32_t lo, hi;
        cvt4(xr[j], lo, hi); sts8(sb0 + sts_off[j], lo, hi);
        cvt4(ar[j], lo, hi); sts8(sb0 + STG_AOFF + sts_off[j], lo, hi);
        asum_p[j] += (ar[j].x + ar[j].y) + (ar[j].z + ar[j].w);
    }
    // stage 1: load into regs only (folded + STS'd at it = 0)
#pragma unroll
    for (int j = 0; j < 4; j++) {
        int ci = tid + 256 * j, row = ci >> 4, c4 = ci & 15;
        xr[j] = *reinterpret_cast<const float4*>(xbase + (size_t)row * NN + NC + (c4 << 2));
        ar[j] = *reinterpret_cast<const float4*>(abase + (size_t)row * NN + NC + (c4 << 2));
    }

    for (int it = 0; it < NITER; ++it) {
        __syncthreads();

        // (1) Drain: fold + cvt + STS stage it+1 (regs loaded one iteration
        //     ago; the fold reads ar BEFORE the LDG below redefines it, so it
        //     can never wait on an in-flight load).
        if (it + 1 < NITER) {
            const uint32_t ns = sb0 + (uint32_t)(((it + 1) & 1)) * STG_BYTES;
#pragma unroll
            for (int j = 0; j < 4; j++) {
                asum_p[j] += (ar[j].x + ar[j].y) + (ar[j].z + ar[j].w);
                uint32_t lo, hi;
                cvt4(xr[j], lo, hi); sts8(ns + sts_off[j], lo, hi);
                cvt4(ar[j], lo, hi); sts8(ns + STG_AOFF + sts_off[j], lo, hi);
            }
        }

        // (2) Refill: LDG stage it+2 (no consumer this iteration)
        if (it + 2 < NITER) {
            const int nb2 = (it + 2) * NC;
#pragma unroll
            for (int j = 0; j < 4; j++) {
                int ci = tid + 256 * j, row = ci >> 4, c4 = ci & 15;
                xr[j] = *reinterpret_cast<const float4*>(xbase + (size_t)row * NN + nb2 + (c4 << 2));
                ar[j] = *reinterpret_cast<const float4*>(abase + (size_t)row * NN + nb2 + (c4 << 2));
            }
        }

        // (3) Compute stage it from buf it&1 (this warp's contraction half)
        const uint32_t bs = sb0 + (uint32_t)(it & 1) * STG_BYTES;
#pragma unroll
        for (int s2 = 0; s2 < 2; s2++) {
            const uint32_t kx = (uint32_t)((2 * nh + s2) << 5);
            uint32_t aF0[4], aF1[4], bF0[4], bF1[4];
            ldsm4(aF0, (bs + offA[0]) ^ kx);
            ldsm4(aF1, (bs + offA[1]) ^ kx);
            ldsm4(bF0, (bs + offB[0]) ^ kx);
            ldsm4(bF1, (bs + offB[1]) ^ kx);
            mma16816(reinterpret_cast<float*>(&accv[0]), aF0, bF0[0], bF0[1]);
            mma16816(reinterpret_cast<float*>(&accv[1]), aF0, bF0[2], bF0[3]);
            mma16816(reinterpret_cast<float*>(&accv[2]), aF0, bF1[0], bF1[1]);
            mma16816(reinterpret_cast<float*>(&accv[3]), aF0, bF1[2], bF1[3]);
            mma16816(reinterpret_cast<float*>(&accv[4]), aF1, bF0[0], bF0[1]);
            mma16816(reinterpret_cast<float*>(&accv[5]), aF1, bF0[2], bF0[3]);
            mma16816(reinterpret_cast<float*>(&accv[6]), aF1, bF1[0], bF1[1]);
            mma16816(reinterpret_cast<float*>(&accv[7]), aF1, bF1[2], bF1[3]);
        }
    }

    // ---- a_sum reduction: k = (tid + 256j) >> 4; 16 consecutive lanes share ----
#pragma unroll
    for (int j = 0; j < 4; j++) {
#pragma unroll
        for (int o = 1; o < 16; o <<= 1)
            asum_p[j] += __shfl_xor_sync(0xFFFFFFFFu, asum_p[j], o);
    }
    if ((lane & 15) == 0) {
        int q = tid >> 4;
#pragma unroll
        for (int j = 0; j < 4; j++) asum_s[q + 16 * j] = asum_p[j];
    }

    // ---- nsplit reduction: warps 4-7 hand partial accs to warps 0-3 ----
    if (nh == 1) {
#pragma unroll
        for (int j4 = 0; j4 < 8; j4++)
            sts16(sb0 + (uint32_t)(j4 * 2048 + (tid & 127) * 16), accv[j4]);
    }
    __syncthreads();

    if (nh == 0) {
#pragma unroll
        for (int j4 = 0; j4 < 8; j4++) {
            float4 p = lds16(sb0 + (uint32_t)(j4 * 2048 + (tid & 127) * 16));
            accv[j4].x += p.x; accv[j4].y += p.y; accv[j4].z += p.z; accv[j4].w += p.w;
        }

        // ---- epilogue: V = wx - a_sum[k]*c[k,d], out[d,k,b] ----
        const int mrow = lane >> 2, ncol = (lane & 3) * 2;
#pragma unroll
        for (int i = 0; i < 2; i++) {
#pragma unroll
            for (int j = 0; j < 4; j++) {
                const float* ap = reinterpret_cast<const float*>(&accv[i * 4 + j]);
                const int k0 = wn + j * 8 + ncol;
                const int d0 = dt * DTILE + wm + i * 16 + mrow;
                const float as0 = asum_s[k0], as1 = asum_s[k0 + 1];
#pragma unroll
                for (int rr = 0; rr < 2; rr++) {
                    const int d = d0 + rr * 8;
                    float v0 = ap[rr * 2 + 0] - as0 * __ldg(cmat + (size_t)k0 * DD + d);
                    float v1 = ap[rr * 2 + 1] - as1 * __ldg(cmat + (size_t)(k0 + 1) * DD + d);
                    out[(size_t)d * KK * BB + (size_t)k0 * BB + b] = v0;
                    out[(size_t)d * KK * BB + (size_t)(k0 + 1) * BB + b] = v1;
                }
            }
        }
    }
}

extern "C" void kernel_launch(void* const* d_in, const int* in_sizes, int n_in,
                              void* d_out, int out_size) {
    (void)in_sizes; (void)n_in; (void)out_size;
    const float* x  = (const float*)d_in[0];
    const float* ab = (const float*)d_in[1];
    const float* c  = (const float*)d_in[2];
    float* out = (float*)d_out;

    cudaFuncSetAttribute(vlad_main, cudaFuncAttributeMaxDynamicSharedMemorySize, SMEM_TOTAL);
    vlad_main<<<BB * 8, 256, SMEM_TOTAL>>>(x, ab, c, out);
}

// round 10
// speedup vs baseline: 2.4437x; 1.0271x over previous
#include <cuda_runtime.h>
#include <cuda_bf16.h>
#include <cstdint>
#include <cstddef>

// Problem constants
#define BB    32
#define DD    512
#define NN    4096
#define KK    64
#define DTILE 64           // d rows per CTA
#define NC    64           // n elements per stage (64 fp32 -> 64 bf16 = 128B row)
#define NITER (NN / NC)    // 64

// SMEM: 4-deep ring of stages (x 8KB + a 8KB each), asum after.
#define STG_BYTES  16384
#define STG_AOFF   8192
#define NBUF       4
#define OFF_ASUM   (NBUF * STG_BYTES)       // 64 floats
#define SMEM_TOTAL (OFF_ASUM + 256 + 1024)  // + alignment slack

__device__ __forceinline__ uint32_t smem_u32(const void* p) {
    uint32_t a;
    asm("{ .reg .u64 t; cvta.to.shared.u64 t, %1; cvt.u32.u64 %0, t; }" : "=r"(a) : "l"(p));
    return a;
}

__device__ __forceinline__ void sts8(uint32_t addr, uint32_t a, uint32_t b) {
    asm volatile("st.shared.v2.b32 [%0], {%1, %2};" :: "r"(addr), "r"(a), "r"(b) : "memory");
}

__device__ __forceinline__ void sts16(uint32_t addr, float4 v) {
    asm volatile("st.shared.v4.b32 [%0], {%1, %2, %3, %4};"
                 :: "r"(addr), "f"(v.x), "f"(v.y), "f"(v.z), "f"(v.w) : "memory");
}

__device__ __forceinline__ float4 lds16(uint32_t addr) {
    float4 v;
    asm volatile("ld.shared.v4.b32 {%0, %1, %2, %3}, [%4];"
                 : "=f"(v.x), "=f"(v.y), "=f"(v.z), "=f"(v.w) : "r"(addr));
    return v;
}

__device__ __forceinline__ void ldsm4(uint32_t* r, uint32_t addr) {
    asm volatile("ldmatrix.sync.aligned.m8n8.x4.shared.b16 {%0,%1,%2,%3}, [%4];"
                 : "=r"(r[0]), "=r"(r[1]), "=r"(r[2]), "=r"(r[3]) : "r"(addr));
}

__device__ __forceinline__ void mma16816(float* d, const uint32_t* a, uint32_t b0, uint32_t b1) {
    asm volatile(
        "mma.sync.aligned.m16n8k16.row.col.f32.bf16.bf16.f32 "
        "{%0,%1,%2,%3}, {%4,%5,%6,%7}, {%8,%9}, {%0,%1,%2,%3};"
        : "+f"(d[0]), "+f"(d[1]), "+f"(d[2]), "+f"(d[3])
        : "r"(a[0]), "r"(a[1]), "r"(a[2]), "r"(a[3]), "r"(b0), "r"(b1));
}

__device__ __forceinline__ void cvt4(const float4& v, uint32_t& lo, uint32_t& hi) {
    __nv_bfloat162 l = __floats2bfloat162_rn(v.x, v.y);
    __nv_bfloat162 h = __floats2bfloat162_rn(v.z, v.w);
    lo = *reinterpret_cast<uint32_t*>(&l);
    hi = *reinterpret_cast<uint32_t*>(&h);
}

// ---------------------------------------------------------------------------
// R9 datapath (line-coalesced loader, 2m x 2n x 2ksplit warp tiling, WAR-
// pinned asum fold, nsplit reduction, fused epilogue) + a 4-deep smem ring
// with __syncthreads only at EVEN iterations (barrier count halved).
// Safety: drains at iter j write stage j+2 (buf (j+2)&3). With syncs at even
// iters, warp skew < 2, so every STS -> ldsm pair and every read -> overwrite
// pair is separated by at least one barrier.
// Per CTA (b, dt): D[64 d, 64 k] = X(64 x 4096) @ Abar^T, bf16 mma.sync,
// fp32 epilogue V = wx - a_sum[k]*c[k,d] -> out[d,k,b].
// ---------------------------------------------------------------------------
__global__ void __launch_bounds__(256, 2)
vlad_main(const float* __restrict__ x, const float* __restrict__ ab,
          const float* __restrict__ cmat, float* __restrict__ out) {
    extern __shared__ __align__(16) char smem_raw[];
    const uint32_t sbr = smem_u32(smem_raw);
    const uint32_t sb0 = (sbr + 1023) & ~1023u;
    float* asum_s = reinterpret_cast<float*>(smem_raw + (sb0 - sbr) + OFF_ASUM);

    const int tid  = threadIdx.x;
    const int warp = tid >> 5, lane = tid & 31;
    const int b  = blockIdx.x >> 3;
    const int dt = blockIdx.x & 7;

    const float* xbase = x  + ((size_t)b * DD + (size_t)dt * DTILE) * NN;
    const float* abase = ab + (size_t)b * KK * NN;

    // STS swizzled offsets: 1024 float4 per tile, 4/thread; ci = tid + 256j
    // -> row = ci>>4 (16 threads cover a full 128B line), c4 = ci&15.
    uint32_t sts_off[4];
#pragma unroll
    for (int j = 0; j < 4; j++) {
        int ci = tid + 256 * j, row = ci >> 4, c4 = ci & 15;
        uint32_t off = (uint32_t)((row << 7) + (c4 << 3));
        sts_off[j] = off ^ ((off >> 3) & 0x70);
    }

    // Warp decomposition: 2(m) x 2(n) x 2(nsplit)
    const int wm = (warp & 1) * 32;
    const int wn = ((warp >> 1) & 1) * 32;
    const int nh = warp >> 2;                 // contraction half: k-steps 2nh, 2nh+1

    // ldmatrix source offsets
    const int g = lane >> 3, r = lane & 7;
    uint32_t offA[2], offB[2];
#pragma unroll
    for (int i = 0; i < 2; i++) {
        int row = wm + i * 16 + (g & 1) * 8 + r;
        uint32_t gk = (uint32_t)((g >> 1) * 16);
        offA[i] = (uint32_t)(row << 7) + (gk ^ (uint32_t)((row & 7) << 4));
    }
#pragma unroll
    for (int nb = 0; nb < 2; nb++) {
        int row = wn + nb * 16 + (g >> 1) * 8 + r;
        uint32_t gk = (uint32_t)((g & 1) * 16);
        offB[nb] = (uint32_t)(row << 7) + (gk ^ (uint32_t)((row & 7) << 4)) + STG_AOFF;
    }

    float4 accv[8];
#pragma unroll
    for (int i = 0; i < 8; i++) accv[i] = make_float4(0.f, 0.f, 0.f, 0.f);
    float asum_p[4] = {0.f, 0.f, 0.f, 0.f};

    float4 xr[4], ar[4];

    // ---- prologue: stages 0 and 1 -> smem (folded), stage 2 -> regs ----
#pragma unroll
    for (int s = 0; s < 2; s++) {
#pragma unroll
        for (int j = 0; j < 4; j++) {
            int ci = tid + 256 * j, row = ci >> 4, c4 = ci & 15;
            xr[j] = *reinterpret_cast<const float4*>(xbase + (size_t)row * NN + s * NC + (c4 << 2));
            ar[j] = *reinterpret_cast<const float4*>(abase + (size_t)row * NN + s * NC + (c4 << 2));
        }
        const uint32_t bufb = sb0 + (uint32_t)s * STG_BYTES;
#pragma unroll
        for (int j = 0; j < 4; j++) {
            uint32_t lo, hi;
            cvt4(xr[j], lo, hi); sts8(bufb + sts_off[j], lo, hi);
            cvt4(ar[j], lo, hi); sts8(bufb + STG_AOFF + sts_off[j], lo, hi);
            asum_p[j] += (ar[j].x + ar[j].y) + (ar[j].z + ar[j].w);
        }
    }
#pragma unroll
    for (int j = 0; j < 4; j++) {
        int ci = tid + 256 * j, row = ci >> 4, c4 = ci & 15;
        xr[j] = *reinterpret_cast<const float4*>(xbase + (size_t)row * NN + 2 * NC + (c4 << 2));
        ar[j] = *reinterpret_cast<const float4*>(abase + (size_t)row * NN + 2 * NC + (c4 << 2));
    }

    for (int it = 0; it < NITER; ++it) {
        if ((it & 1) == 0) __syncthreads();

        // (1) Drain: fold + cvt + STS stage it+2 into buf (it+2)&3.
        //     Regs were loaded one iteration ago; the fold reads ar BEFORE
        //     the LDG below redefines it (WAR), so it never waits on loads.
        if (it + 2 < NITER) {
            const uint32_t ns = sb0 + (uint32_t)((it + 2) & (NBUF - 1)) * STG_BYTES;
#pragma unroll
            for (int j = 0; j < 4; j++) {
                asum_p[j] += (ar[j].x + ar[j].y) + (ar[j].z + ar[j].w);
                uint32_t lo, hi;
                cvt4(xr[j], lo, hi); sts8(ns + sts_off[j], lo, hi);
                cvt4(ar[j], lo, hi); sts8(ns + STG_AOFF + sts_off[j], lo, hi);
            }
        }

        // (2) Refill: LDG stage it+3 (consumed at next iteration's drain)
        if (it + 3 < NITER) {
            const int nb2 = (it + 3) * NC;
#pragma unroll
            for (int j = 0; j < 4; j++) {
                int ci = tid + 256 * j, row = ci >> 4, c4 = ci & 15;
                xr[j] = *reinterpret_cast<const float4*>(xbase + (size_t)row * NN + nb2 + (c4 << 2));
                ar[j] = *reinterpret_cast<const float4*>(abase + (size_t)row * NN + nb2 + (c4 << 2));
            }
        }

        // (3) Compute stage it from buf it&3 (this warp's contraction half)
        const uint32_t bs = sb0 + (uint32_t)(it & (NBUF - 1)) * STG_BYTES;
#pragma unroll
        for (int s2 = 0; s2 < 2; s2++) {
            const uint32_t kx = (uint32_t)((2 * nh + s2) << 5);
            uint32_t aF0[4], aF1[4], bF0[4], bF1[4];
            ldsm4(aF0, (bs + offA[0]) ^ kx);
            ldsm4(aF1, (bs + offA[1]) ^ kx);
            ldsm4(bF0, (bs + offB[0]) ^ kx);
            ldsm4(bF1, (bs + offB[1]) ^ kx);
            mma16816(reinterpret_cast<float*>(&accv[0]), aF0, bF0[0], bF0[1]);
            mma16816(reinterpret_cast<float*>(&accv[1]), aF0, bF0[2], bF0[3]);
            mma16816(reinterpret_cast<float*>(&accv[2]), aF0, bF1[0], bF1[1]);
            mma16816(reinterpret_cast<float*>(&accv[3]), aF0, bF1[2], bF1[3]);
            mma16816(reinterpret_cast<float*>(&accv[4]), aF1, bF0[0], bF0[1]);
            mma16816(reinterpret_cast<float*>(&accv[5]), aF1, bF0[2], bF0[3]);
            mma16816(reinterpret_cast<float*>(&accv[6]), aF1, bF1[0], bF1[1]);
            mma16816(reinterpret_cast<float*>(&accv[7]), aF1, bF1[2], bF1[3]);
        }
    }

    // ---- a_sum reduction: k = (tid + 256j) >> 4; 16 consecutive lanes share ----
#pragma unroll
    for (int j = 0; j < 4; j++) {
#pragma unroll
        for (int o = 1; o < 16; o <<= 1)
            asum_p[j] += __shfl_xor_sync(0xFFFFFFFFu, asum_p[j], o);
    }
    if ((lane & 15) == 0) {
        int q = tid >> 4;
#pragma unroll
        for (int j = 0; j < 4; j++) asum_s[q + 16 * j] = asum_p[j];
    }

    // ---- nsplit reduction (uses buf0 region; last read of buf0 was iter 60,
    //      all warps passed the iter-62 sync, so no overlap) ----
    if (nh == 1) {
#pragma unroll
        for (int j4 = 0; j4 < 8; j4++)
            sts16(sb0 + (uint32_t)(j4 * 2048 + (tid & 127) * 16), accv[j4]);
    }
    __syncthreads();

    if (nh == 0) {
#pragma unroll
        for (int j4 = 0; j4 < 8; j4++) {
            float4 p = lds16(sb0 + (uint32_t)(j4 * 2048 + (tid & 127) * 16));
            accv[j4].x += p.x; accv[j4].y += p.y; accv[j4].z += p.z; accv[j4].w += p.w;
        }

        // ---- epilogue: V = wx - a_sum[k]*c[k,d], out[d,k,b] ----
        const int mrow = lane >> 2, ncol = (lane & 3) * 2;
#pragma unroll
        for (int i = 0; i < 2; i++) {
#pragma unroll
            for (int j = 0; j < 4; j++) {
                const float* ap = reinterpret_cast<const float*>(&accv[i * 4 + j]);
                const int k0 = wn + j * 8 + ncol;
                const int d0 = dt * DTILE + wm + i * 16 + mrow;
                const float as0 = asum_s[k0], as1 = asum_s[k0 + 1];
#pragma unroll
                for (int rr = 0; rr < 2; rr++) {
                    const int d = d0 + rr * 8;
                    float v0 = ap[rr * 2 + 0] - as0 * __ldg(cmat + (size_t)k0 * DD + d);
                    float v1 = ap[rr * 2 + 1] - as1 * __ldg(cmat + (size_t)(k0 + 1) * DD + d);
                    out[(size_t)d * KK * BB + (size_t)k0 * BB + b] = v0;
                    out[(size_t)d * KK * BB + (size_t)(k0 + 1) * BB + b] = v1;
                }
            }
        }
    }
}

extern "C" void kernel_launch(void* const* d_in, const int* in_sizes, int n_in,
                              void* d_out, int out_size) {
    (void)in_sizes; (void)n_in; (void)out_size;
    const float* x  = (const float*)d_in[0];
    const float* ab = (const float*)d_in[1];
    const float* c  = (const float*)d_in[2];
    float* out = (float*)d_out;

    cudaFuncSetAttribute(vlad_main, cudaFuncAttributeMaxDynamicSharedMemorySize, SMEM_TOTAL);
    vlad_main<<<BB * 8, 256, SMEM_TOTAL>>>(x, ab, c, out);
}